// round 17
// baseline (speedup 1.0000x reference)
#include <cuda_runtime.h>
#include <cuda_fp16.h>
#include <cstdint>

#define D_MODEL 1024
#define BATCH   8
#define SEQ     2048
#define NROWS   (BATCH * SEQ)

// -------- scratch: static device globals (allocation-free contract) --------
__device__ __half g_xh [(size_t)NROWS * D_MODEL];
__device__ __half g_Wh [(size_t)3 * D_MODEL * D_MODEL];      // [Wq;Wk;Wv] packed
__device__ __half g_Qh [(size_t)NROWS * D_MODEL];
__device__ __half g_Kh [(size_t)NROWS * D_MODEL];
__device__ __half g_Vth[(size_t)BATCH * D_MODEL * SEQ];      // V^T: [b][o][tok]
__device__ float  g_S  [(size_t)BATCH * SEQ * SEQ];
__device__ __half g_P  [(size_t)BATCH * SEQ * SEQ];

// ---- tiling: 128x128 CTA / 256 thr / 2 CTAs per SM / 128B k-tiles ----
#define BM 128
#define BN 128
#define BKH 64
#define STAGES 3
#define ROW_B 144       // 128B data + 16B pad (36-bank stride: ldmatrix conflict-free)
#define STAGE_A (BM * ROW_B)
#define STAGE_B (BN * ROW_B)
#define STAGE_BYTES (STAGE_A + STAGE_B)
#define SMEM_TOTAL (STAGES * STAGE_BYTES)   // 110592 B -> 2 CTAs/SM

// ---------------- ptx helpers ----------------
__device__ __forceinline__ uint32_t s2u(const void* p) {
    uint32_t a;
    asm("{ .reg .u64 t; cvta.to.shared.u64 t, %1; cvt.u32.u64 %0, t; }" : "=r"(a) : "l"(p));
    return a;
}
__device__ __forceinline__ void cp16(uint32_t dst, const void* src) {
    asm volatile("cp.async.cg.shared.global [%0], [%1], 16;" :: "r"(dst), "l"(src));
}
#define CP_COMMIT() asm volatile("cp.async.commit_group;" ::: "memory")
#define CP_WAIT(n)  asm volatile("cp.async.wait_group %0;" :: "n"(n) : "memory")

__device__ __forceinline__ void ldmx4(uint32_t* r, uint32_t a) {
    asm volatile("ldmatrix.sync.aligned.m8n8.x4.shared.b16 {%0,%1,%2,%3}, [%4];"
        : "=r"(r[0]), "=r"(r[1]), "=r"(r[2]), "=r"(r[3]) : "r"(a));
}
__device__ __forceinline__ void mma16816(float* c, const uint32_t* a, const uint32_t* b) {
    asm volatile(
        "mma.sync.aligned.m16n8k16.row.col.f32.f16.f16.f32 "
        "{%0,%1,%2,%3},{%4,%5,%6,%7},{%8,%9},{%0,%1,%2,%3};"
        : "+f"(c[0]), "+f"(c[1]), "+f"(c[2]), "+f"(c[3])
        : "r"(a[0]), "r"(a[1]), "r"(a[2]), "r"(a[3]), "r"(b[0]), "r"(b[1]));
}

// ---------------- fp16 NT GEMM:  C = scale * A @ B^T ----------------
// MODE 4: fused QKV projection.  MODE 2: S gemm (causal skip).  MODE 3: PV gemm (K-truncated).
template<int MODE>
__global__ void __launch_bounds__(256, 2)
gemm_h(const __half* __restrict__ Ag, const __half* __restrict__ Bg, void* __restrict__ Cv,
       int K_, int Ng, long long sA, long long sB, long long sC, float scale,
       __half* __restrict__ Cq, __half* __restrict__ Ck, __half* __restrict__ Cvt)
{
    extern __shared__ char smem_raw[];
    const int my = (MODE == 3) ? ((int)gridDim.y - 1 - (int)blockIdx.y) : (int)blockIdx.y;
    const int m0 = my * BM;
    const int n0 = blockIdx.x * BN;
    if (MODE == 2 && n0 >= m0 + BM) return;

    const __half* A = Ag + (size_t)blockIdx.z * sA;
    const __half* B = Bg + (size_t)blockIdx.z * sB;

    const int kEnd = (MODE == 3) ? (m0 + BM) : K_;
    const int NT   = kEnd / BKH;

    const uint32_t sbase = s2u(smem_raw);
    const int tid  = threadIdx.x;
    const int wid  = tid >> 5;
    const int lane = tid & 31;
    const int wm = (wid & 1) * 64;
    const int wn = (wid >> 1) * 32;
    const int g  = lane >> 2;
    const int tq = lane & 3;
    const int ld_r = tid >> 3;
    const int ld_c = (tid & 7) * 16;
    const int ld_k = (tid & 7) * 8;

    auto issue = [&](int kt) {
        if (kt < NT) {
            const uint32_t stage = sbase + (kt % STAGES) * STAGE_BYTES;
            const size_t kcol = (size_t)(kt * BKH + ld_k);
            #pragma unroll
            for (int j = 0; j < 4; j++) {
                const int row = ld_r + j * 32;
                cp16(stage + row * ROW_B + ld_c,           A + (size_t)(m0 + row) * K_ + kcol);
                cp16(stage + STAGE_A + row * ROW_B + ld_c, B + (size_t)(n0 + row) * K_ + kcol);
            }
        }
        CP_COMMIT();
    };

    issue(0);
    issue(1);

    float acc[4][4][4];
    #pragma unroll
    for (int i = 0; i < 4; i++)
        #pragma unroll
        for (int j = 0; j < 4; j++)
            #pragma unroll
            for (int r = 0; r < 4; r++) acc[i][j][r] = 0.f;

    const int l7 = lane & 7;
    const int sel = lane >> 3;

    for (int kt = 0; kt < NT; kt++) {
        CP_WAIT(STAGES - 2);
        __syncthreads();
        issue(kt + STAGES - 1);   // refill slot all readers just vacated

        const uint32_t ab = sbase + (kt % STAGES) * STAGE_BYTES;
        const uint32_t bb = ab + STAGE_A;
        #pragma unroll
        for (int ks = 0; ks < 4; ks++) {
            uint32_t af[4][4], bf[4][2];
            #pragma unroll
            for (int mt = 0; mt < 4; mt++) {
                const int row = wm + mt * 16 + l7 + ((sel & 1) << 3);
                const int ch  = ks * 2 + (sel >> 1);
                ldmx4(af[mt], ab + row * ROW_B + ch * 16);
            }
            #pragma unroll
            for (int p = 0; p < 2; p++) {
                const int nrow = wn + p * 16 + ((sel >> 1) << 3) + l7;
                const int ch   = ks * 2 + (sel & 1);
                uint32_t r[4];
                ldmx4(r, bb + nrow * ROW_B + ch * 16);
                bf[p * 2][0]     = r[0]; bf[p * 2][1]     = r[1];
                bf[p * 2 + 1][0] = r[2]; bf[p * 2 + 1][1] = r[3];
            }
            #pragma unroll
            for (int mt = 0; mt < 4; mt++)
                #pragma unroll
                for (int nt = 0; nt < 4; nt++)
                    mma16816(acc[mt][nt], af[mt], bf[nt]);
        }
    }

    // ---------------- epilogue ----------------
    if (MODE == 4) {
        const int sector = n0 >> 10;
        const int nc0 = n0 & 1023;
        if (sector < 2) {
            __half* C = sector ? Ck : Cq;
            #pragma unroll
            for (int mt = 0; mt < 4; mt++) {
                const int r0 = m0 + wm + mt * 16 + g;
                #pragma unroll
                for (int nt = 0; nt < 4; nt++) {
                    const int c = nc0 + wn + nt * 8 + tq * 2;
                    *reinterpret_cast<__half2*>(C + (size_t)r0 * D_MODEL + c) =
                        __floats2half2_rn(acc[mt][nt][0], acc[mt][nt][1]);
                    *reinterpret_cast<__half2*>(C + (size_t)(r0 + 8) * D_MODEL + c) =
                        __floats2half2_rn(acc[mt][nt][2], acc[mt][nt][3]);
                }
            }
        } else {
            CP_WAIT(0);
            __syncthreads();
            __half* hbuf = reinterpret_cast<__half*>(smem_raw + wid * 4608);
            #pragma unroll
            for (int mt = 0; mt < 4; mt++) {
                const int t0 = mt * 16 + g;
                #pragma unroll
                for (int nt = 0; nt < 4; nt++) {
                    const int c = nt * 8 + tq * 2;
                    hbuf[(c    ) * 72 + t0    ] = __float2half_rn(acc[mt][nt][0]);
                    hbuf[(c + 1) * 72 + t0    ] = __float2half_rn(acc[mt][nt][1]);
                    hbuf[(c    ) * 72 + t0 + 8] = __float2half_rn(acc[mt][nt][2]);
                    hbuf[(c + 1) * 72 + t0 + 8] = __float2half_rn(acc[mt][nt][3]);
                }
            }
            __syncwarp();
            const int b = m0 >> 11;
            const int tok0 = (m0 & (SEQ - 1)) + wm;
            const int o = nc0 + wn + lane;
            const uint4* src = reinterpret_cast<const uint4*>(hbuf + lane * 72);
            uint4* dst = reinterpret_cast<uint4*>(Cvt + ((size_t)(b * D_MODEL + o)) * SEQ + tok0);
            #pragma unroll
            for (int u = 0; u < 8; u++) dst[u] = src[u];
        }
    } else {
        float* C = (float*)Cv + (size_t)blockIdx.z * sC;
        #pragma unroll
        for (int mt = 0; mt < 4; mt++) {
            const int r0 = m0 + wm + mt * 16 + g;
            #pragma unroll
            for (int nt = 0; nt < 4; nt++) {
                const int c = n0 + wn + nt * 8 + tq * 2;
                const float2 v0 = make_float2(acc[mt][nt][0] * scale, acc[mt][nt][1] * scale);
                const float2 v1 = make_float2(acc[mt][nt][2] * scale, acc[mt][nt][3] * scale);
                *reinterpret_cast<float2*>(C + (size_t)r0 * Ng + c) = v0;
                *reinterpret_cast<float2*>(C + (size_t)(r0 + 8) * Ng + c) = v1;
            }
        }
    }
}

// -------- merged weight conversion: Wq, Wk, Wv in a single launch --------
__global__ void __launch_bounds__(256) f2h_w3(const float4* __restrict__ w0,
                                              const float4* __restrict__ w1,
                                              const float4* __restrict__ w2,
                                              __half2* __restrict__ d, int n4seg)
{
    const int i = blockIdx.x * blockDim.x + threadIdx.x;   // grid == 3*n4seg threads
    const int seg = i / n4seg;
    const int idx = i - seg * n4seg;
    const float4* s = (seg == 0) ? w0 : (seg == 1) ? w1 : w2;
    const float4 v = s[idx];
    __half2* dd = d + (size_t)seg * n4seg * 2;
    dd[2 * idx]     = __floats2half2_rn(v.x, v.y);
    dd[2 * idx + 1] = __floats2half2_rn(v.z, v.w);
}

// ---------------- x conversion ----------------
__global__ void __launch_bounds__(256) f2h(const float4* __restrict__ s,
                                           __half2* __restrict__ d, int n4)
{
    const int i = blockIdx.x * blockDim.x + threadIdx.x;
    if (i < n4) {
        const float4 v = s[i];
        d[2 * i]     = __floats2half2_rn(v.x, v.y);
        d[2 * i + 1] = __floats2half2_rn(v.z, v.w);
    }
}

// ---- causal softmax: S fp32 -> P fp16; work truncated at the causal block edge ----
// Restructured loops (unrolled max-extent with early break) — semantics unchanged:
// skipped blocks are entirely masked (contribute -inf to max, 0 to sum).
__global__ void __launch_bounds__(256) softmax_causal(const float* __restrict__ S,
                                                      __half* __restrict__ P)
{
    __shared__ float red[8];
    const int row = blockIdx.x;
    const int qi  = row & (SEQ - 1);
    const int L   = qi + 1;
    const int Wl  = (qi | 127) + 1;    // == PV kEnd for this row's block; even
    const int NB  = (Wl + 511) >> 9;   // active 512-wide blocks (1..4)
    const float* s = S + (size_t)row * SEQ;
    __half* p = P + (size_t)row * SEQ;
    const int tid = threadIdx.x;

    float vx[4], vy[4];
    float m = -3.4e38f;
    #pragma unroll
    for (int it = 0; it < 4; it++) {
        if (it >= NB) break;
        const int j2 = (tid + it * 256) * 2;
        const float2 val = *reinterpret_cast<const float2*>(s + j2);  // in-bounds read
        vx[it] = (j2     < L) ? val.x : -3.4e38f;
        vy[it] = (j2 + 1 < L) ? val.y : -3.4e38f;
        m = fmaxf(m, fmaxf(vx[it], vy[it]));
    }
    #pragma unroll
    for (int o = 16; o; o >>= 1) m = fmaxf(m, __shfl_xor_sync(0xffffffffu, m, o));
    if ((tid & 31) == 0) red[tid >> 5] = m;
    __syncthreads();
    m = red[0];
    #pragma unroll
    for (int w = 1; w < 8; w++) m = fmaxf(m, red[w]);
    __syncthreads();

    float sum = 0.f;
    #pragma unroll
    for (int it = 0; it < 4; it++) {
        if (it >= NB) break;
        const int j2 = (tid + it * 256) * 2;
        const float ex = (j2     < L) ? __expf(vx[it] - m) : 0.f;
        const float ey = (j2 + 1 < L) ? __expf(vy[it] - m) : 0.f;
        vx[it] = ex; vy[it] = ey;
        sum += ex + ey;
    }
    #pragma unroll
    for (int o = 16; o; o >>= 1) sum += __shfl_xor_sync(0xffffffffu, sum, o);
    if ((tid & 31) == 0) red[tid >> 5] = sum;
    __syncthreads();
    sum = 0.f;
    #pragma unroll
    for (int w = 0; w < 8; w++) sum += red[w];
    const float inv = 1.f / sum;

    #pragma unroll
    for (int it = 0; it < 4; it++) {
        if (it >= NB) break;
        const int j2 = (tid + it * 256) * 2;
        if (j2 < Wl)
            *reinterpret_cast<__half2*>(p + j2) =
                __floats2half2_rn(vx[it] * inv, vy[it] * inv);
    }
}

// ---------------- launch ----------------
extern "C" void kernel_launch(void* const* d_in, const int* in_sizes, int n_in,
                              void* d_out, int out_size)
{
    const float* x  = (const float*)d_in[0];
    const float* Wq = (const float*)d_in[1];
    const float* Wk = (const float*)d_in[2];
    const float* Wv = (const float*)d_in[3];
    float* out = (float*)d_out;

    __half *pxh, *pWh, *pQh, *pKh, *pVth, *pP;
    float *pS;
    cudaGetSymbolAddress((void**)&pxh,  g_xh);
    cudaGetSymbolAddress((void**)&pWh,  g_Wh);
    cudaGetSymbolAddress((void**)&pQh,  g_Qh);
    cudaGetSymbolAddress((void**)&pKh,  g_Kh);
    cudaGetSymbolAddress((void**)&pVth, g_Vth);
    cudaGetSymbolAddress((void**)&pS,   g_S);
    cudaGetSymbolAddress((void**)&pP,   g_P);

    cudaFuncSetAttribute(gemm_h<4>, cudaFuncAttributeMaxDynamicSharedMemorySize, SMEM_TOTAL);
    cudaFuncSetAttribute(gemm_h<2>, cudaFuncAttributeMaxDynamicSharedMemorySize, SMEM_TOTAL);
    cudaFuncSetAttribute(gemm_h<3>, cudaFuncAttributeMaxDynamicSharedMemorySize, SMEM_TOTAL);

    const int WSZ = D_MODEL * D_MODEL;

    // 0) conversions
    {
        const int w4 = WSZ / 4;
        f2h_w3<<<3 * w4 / 256, 256>>>((const float4*)Wq, (const float4*)Wk,
                                      (const float4*)Wv, (__half2*)pWh, w4);
        const int n4 = NROWS * D_MODEL / 4;
        f2h<<<(n4 + 255) / 256, 256>>>((const float4*)x, (__half2*)pxh, n4);
    }

    const dim3 blk(256);

    // 1) fused QKV projection
    {
        dim3 grid(3 * D_MODEL / BN, NROWS / BM, 1);
        gemm_h<4><<<grid, blk, SMEM_TOTAL>>>(pxh, pWh, nullptr, D_MODEL, 3 * D_MODEL,
                                             0, 0, 0, 1.f, pQh, pKh, pVth);
    }

    // 2) S = (Q @ K^T) / 32, causal tile skip  (launch 3: ncu window)
    {
        dim3 grid(SEQ / BN, SEQ / BM, BATCH);
        gemm_h<2><<<grid, blk, SMEM_TOTAL>>>(pQh, pKh, pS, D_MODEL, SEQ,
                                             (long long)SEQ * D_MODEL,
                                             (long long)SEQ * D_MODEL,
                                             (long long)SEQ * SEQ, 0.03125f,
                                             nullptr, nullptr, nullptr);
    }

    // 3) causal softmax
    softmax_causal<<<NROWS, 256>>>(pS, pP);

    // 4) O = P @ Vt^T, K truncated, longest m-tiles first
    {
        dim3 grid(D_MODEL / BN, SEQ / BM, BATCH);
        gemm_h<3><<<grid, blk, SMEM_TOTAL>>>(pP, pVth, out, SEQ, D_MODEL,
                                             (long long)SEQ * SEQ,
                                             (long long)D_MODEL * SEQ,
                                             (long long)SEQ * D_MODEL, 1.f,
                                             nullptr, nullptr, nullptr);
    }
}